// round 1
// baseline (speedup 1.0000x reference)
#include <cuda_runtime.h>
#include <math.h>

// Problem shape (fixed by the dataset): features [8, 4096, 256] f32, scores [8, 4096, 1] f32.
#define BB 8
#define NN 4096
#define DD 256
#define ROWS_PER_WARP 8
#define WARPS 8
#define ROWS_PER_BLOCK (ROWS_PER_WARP * WARPS)      // 64
#define NBLOCKS ((BB * NN) / ROWS_PER_BLOCK)        // 512
#define BLOCKS_PER_B (NN / ROWS_PER_BLOCK)          // 64

// Scratch (device globals: no allocation allowed in kernel_launch).
__device__ float g_inv[BB * NN];            // 1 / max(||x_row||, eps)
__device__ float g_part[NBLOCKS][DD];       // per-block partial of sum_n f[b,n,:]
__device__ float g_sumv[BB][DD];            // S_b = sum_n f[b,n,:]
__device__ float g_sum2[BB];                // ||S_b||^2
__device__ float g_bce[NBLOCKS];            // per-block partial of BCE numerator

// ---------------------------------------------------------------------------
// Pass 1: per-row inverse norms + per-block partial sums of normalized rows.
// Each warp handles 8 consecutive rows; lane owns 8 fixed d-indices
// (d = lane*4..lane*4+3 and 128+lane*4..128+lane*4+3) via two float4 loads.
// ---------------------------------------------------------------------------
__global__ void __launch_bounds__(256) k_norm(const float* __restrict__ feat) {
    __shared__ float sp[WARPS][DD];
    const int w = threadIdx.x >> 5, lane = threadIdx.x & 31;
    const int r0 = blockIdx.x * ROWS_PER_BLOCK + w * ROWS_PER_WARP;
    const float4* fp = (const float4*)feat;

    float a0 = 0.f, a1 = 0.f, a2 = 0.f, a3 = 0.f;
    float a4 = 0.f, a5 = 0.f, a6 = 0.f, a7 = 0.f;
    float myinv = 0.f;

#pragma unroll
    for (int j = 0; j < ROWS_PER_WARP; j++) {
        const int r = r0 + j;
        float4 a = fp[r * 64 + lane];
        float4 c = fp[r * 64 + 32 + lane];
        float ss = a.x * a.x + a.y * a.y + a.z * a.z + a.w * a.w
                 + c.x * c.x + c.y * c.y + c.z * c.z + c.w * c.w;
#pragma unroll
        for (int o = 16; o > 0; o >>= 1)
            ss += __shfl_xor_sync(0xffffffffu, ss, o);
        // F.normalize eps: 1/max(||x||, 1e-12)
        float inv = 1.0f / fmaxf(sqrtf(ss), 1e-12f);
        if (lane == j) myinv = inv;
        a0 += a.x * inv; a1 += a.y * inv; a2 += a.z * inv; a3 += a.w * inv;
        a4 += c.x * inv; a5 += c.y * inv; a6 += c.z * inv; a7 += c.w * inv;
    }
    if (lane < ROWS_PER_WARP) g_inv[r0 + lane] = myinv;

    sp[w][lane * 4 + 0] = a0; sp[w][lane * 4 + 1] = a1;
    sp[w][lane * 4 + 2] = a2; sp[w][lane * 4 + 3] = a3;
    sp[w][128 + lane * 4 + 0] = a4; sp[w][128 + lane * 4 + 1] = a5;
    sp[w][128 + lane * 4 + 2] = a6; sp[w][128 + lane * 4 + 3] = a7;
    __syncthreads();

    const int d = threadIdx.x;   // 0..255
    float s = sp[0][d];
#pragma unroll
    for (int i = 1; i < WARPS; i++) s += sp[i][d];
    g_part[blockIdx.x][d] = s;
}

// ---------------------------------------------------------------------------
// Pass 2: reduce the 64 per-block partials into S_b, and compute ||S_b||^2
// with a deterministic shared-memory tree.
// ---------------------------------------------------------------------------
__global__ void __launch_bounds__(256) k_sum(void) {
    const int b = blockIdx.x, d = threadIdx.x;
    float s = 0.f;
#pragma unroll 8
    for (int i = 0; i < BLOCKS_PER_B; i++) s += g_part[b * BLOCKS_PER_B + i][d];
    g_sumv[b][d] = s;

    __shared__ float sh[DD];
    sh[d] = s * s;
    __syncthreads();
    for (int st = 128; st > 0; st >>= 1) {
        if (d < st) sh[d] += sh[d + st];
        __syncthreads();
    }
    if (d == 0) g_sum2[b] = sh[0];
}

// ---------------------------------------------------------------------------
// Pass 3: per-row dot(x, S_b) * inv -> similarity -> target -> BCE terms.
// Warp computes 8 row-dots (butterfly reduce gives identical value to all
// lanes); lane j stashes dot of row j so the logf/log1pf epilogue runs
// 8-lanes-wide instead of serialized on lane 0.
// ---------------------------------------------------------------------------
__global__ void __launch_bounds__(256) k_bce(const float* __restrict__ feat,
                                             const float* __restrict__ scores) {
    __shared__ float4 sv[64];          // S_b as float4[64]
    __shared__ float sbce[WARPS];
    const int b = blockIdx.x / BLOCKS_PER_B;
    if (threadIdx.x < 64) sv[threadIdx.x] = ((const float4*)g_sumv[b])[threadIdx.x];
    __syncthreads();

    const int w = threadIdx.x >> 5, lane = threadIdx.x & 31;
    const float4 sA = sv[lane];
    const float4 sB = sv[32 + lane];
    const int r0 = blockIdx.x * ROWS_PER_BLOCK + w * ROWS_PER_WARP;
    const float4* fp = (const float4*)feat;

    float mydot = 0.f;
#pragma unroll
    for (int j = 0; j < ROWS_PER_WARP; j++) {
        const int r = r0 + j;
        float4 a = fp[r * 64 + lane];
        float4 c = fp[r * 64 + 32 + lane];
        float dt = a.x * sA.x + a.y * sA.y + a.z * sA.z + a.w * sA.w
                 + c.x * sB.x + c.y * sB.y + c.z * sB.z + c.w * sB.w;
#pragma unroll
        for (int o = 16; o > 0; o >>= 1)
            dt += __shfl_xor_sync(0xffffffffu, dt, o);
        if (lane == j) mydot = dt;
    }

    float term = 0.f;
    if (lane < ROWS_PER_WARP) {
        const int r = r0 + lane;
        const float inv = g_inv[r];
        // similarity = (f . S - 1) / (N - 1); target = 1 - relu(similarity)
        const float sim = (mydot * inv - 1.0f) * (1.0f / (float)(NN - 1));
        const float t = 1.0f - fmaxf(sim, 0.0f);
        const float sc = scores[r];
        const float ls = fmaxf(logf(sc), -100.0f);      // clamp like torch BCELoss
        const float l1 = fmaxf(log1pf(-sc), -100.0f);
        term = t * ls + (1.0f - t) * l1;
    }
#pragma unroll
    for (int o = 16; o > 0; o >>= 1)
        term += __shfl_xor_sync(0xffffffffu, term, o);
    if (lane == 0) sbce[w] = term;
    __syncthreads();

    if (threadIdx.x == 0) {
        float s = 0.f;
#pragma unroll
        for (int i = 0; i < WARPS; i++) s += sbce[i];
        g_bce[blockIdx.x] = s;
    }
}

// ---------------------------------------------------------------------------
// Final: deterministic tree over 512 BCE partials + 8 ||S_b||^2, write scalar.
//   bce       = -sum(term) / (B*N)
//   feat_loss = 1 - sum_b ||S_b||^2 / (B*N*N)     [mean(gram) identity]
// ---------------------------------------------------------------------------
__global__ void __launch_bounds__(512) k_final(float* __restrict__ out) {
    __shared__ float sh[NBLOCKS];
    const int t = threadIdx.x;
    sh[t] = g_bce[t];
    __syncthreads();
    for (int st = 256; st > 0; st >>= 1) {
        if (t < st) sh[t] += sh[t + st];
        __syncthreads();
    }
    if (t == 0) {
        float s2 = 0.f;
#pragma unroll
        for (int b = 0; b < BB; b++) s2 += g_sum2[b];
        const float bce = -sh[0] / (float)(BB * NN);
        const float feat_loss = 1.0f - s2 / ((float)BB * (float)NN * (float)NN);
        out[0] = bce + feat_loss;
    }
}

extern "C" void kernel_launch(void* const* d_in, const int* in_sizes, int n_in,
                              void* d_out, int out_size) {
    const float* feat = (const float*)d_in[0];    // [8, 4096, 256] f32
    const float* scores = (const float*)d_in[1];  // [8, 4096, 1]  f32
    float* out = (float*)d_out;                   // scalar f32

    k_norm<<<NBLOCKS, 256>>>(feat);
    k_sum<<<BB, 256>>>();
    k_bce<<<NBLOCKS, 256>>>(feat, scores);
    k_final<<<1, 512>>>(out);
}